// round 5
// baseline (speedup 1.0000x reference)
#include <cuda_runtime.h>
#include <cuda_bf16.h>
#include <cstdint>

// MHC layer: B=8192, N=4, C=4096, f32. HBM-bound fusion.
// R5: 1 CTA/SM x 1024 thr, THREE row buffers (192KB), ONE barrier per row.
// - prefetch row r+1 while processing row r (cp.async depth 1)
// - reduce: warp shuffle -> partials -> 1 syncthreads -> every thread sums
//   the 32 partials itself (broadcast LDS), parity-double-buffered.
// - trailing buffer-protection barrier eliminated by 3-buffer rotation.

#define C_DIM 4096
#define NS 4
#define THREADS 1024            // = C_DIM/4 -> one float4 per stream per thread
#define ROWS_PER_CTA 8
#define EPS 1e-6f
#define ROW_F4 (NS * C_DIM / 4)             // 4096 float4 per row buffer
#define SMEM_BYTES (3 * ROW_F4 * 16)        // 192 KB: three row buffers

__device__ __forceinline__ uint32_t smem_u32(const void* p) {
    uint32_t a;
    asm("{ .reg .u64 t; cvta.to.shared.u64 t, %1; cvt.u32.u64 %0, t; }"
        : "=r"(a) : "l"(p));
    return a;
}

__global__ __launch_bounds__(THREADS, 1)
void mhc_kernel(const float* __restrict__ x,
                const float* __restrict__ w,
                const float* __restrict__ H_pre,
                const float* __restrict__ H_post,
                const float* __restrict__ H_res,
                float* __restrict__ out)
{
    extern __shared__ float4 sx[];          // [3][ROW_F4]
    __shared__ float4 red4[2][THREADS / 32 / 4];   // [parity][8] = 32 floats
    __shared__ float sp[24];                // [0:4)=hpre [4:8)=hpost [8:24)=P

    const int t = threadIdx.x;
    const int b0 = blockIdx.x * ROWS_PER_CTA;
    const uint32_t sbase = smem_u32(sx);

    // ---- prologue: prefetch first row into buffer 0 ----
    {
        const float4* __restrict__ xr =
            reinterpret_cast<const float4*>(x + (size_t)b0 * NS * C_DIM);
#pragma unroll
        for (int n = 0; n < NS; n++) {
            const int idx = n * THREADS + t;
            asm volatile("cp.async.cg.shared.global [%0], [%1], 16;"
                         :: "r"(sbase + idx * 16), "l"(xr + idx));
        }
        asm volatile("cp.async.commit_group;");
    }

    // ---- thread 0: tiny parameter math into smem while copies fly ----
    if (t == 0) {
#pragma unroll
        for (int n = 0; n < NS; n++) {
            sp[n]     = 1.0f / (1.0f + expf(-H_pre[n]));
            sp[4 + n] = 2.0f / (1.0f + expf(-H_post[n]));
        }
        float P[NS][NS];
#pragma unroll
        for (int i = 0; i < NS; i++)
#pragma unroll
            for (int j = 0; j < NS; j++)
                P[i][j] = expf(H_res[i * NS + j]);
#pragma unroll
        for (int it = 0; it < 3; it++) {
#pragma unroll
            for (int i = 0; i < NS; i++) {
                float inv = 1.0f / (P[i][0] + P[i][1] + P[i][2] + P[i][3] + EPS);
#pragma unroll
                for (int j = 0; j < NS; j++) P[i][j] *= inv;
            }
#pragma unroll
            for (int j = 0; j < NS; j++) {
                float inv = 1.0f / (P[0][j] + P[1][j] + P[2][j] + P[3][j] + EPS);
#pragma unroll
                for (int i = 0; i < NS; i++) P[i][j] *= inv;
            }
        }
#pragma unroll
        for (int i = 0; i < NS; i++)
#pragma unroll
            for (int j = 0; j < NS; j++)
                sp[8 + i * NS + j] = P[i][j];
    }
    __syncthreads();

    // ---- params into registers ----
    const float hp0 = sp[0], hp1 = sp[1], hp2 = sp[2], hp3 = sp[3];
    float Pr[NS][NS], hq[NS];
#pragma unroll
    for (int i = 0; i < NS; i++) {
        hq[i] = sp[4 + i];
#pragma unroll
        for (int j = 0; j < NS; j++) Pr[i][j] = sp[8 + i * NS + j];
    }

    const float4* __restrict__ wr = reinterpret_cast<const float4*>(w);
    const float4 w4 = wr[t];                // weight chunk: loop-invariant

#pragma unroll 1
    for (int r = 0; r < ROWS_PER_CTA; r++) {
        const int b = b0 + r;
        const bool has_next = (r + 1 < ROWS_PER_CTA);
        const int cur = r % 3;
        const int par = r & 1;

        // ---- prefetch row r+1 into buf[(r+1)%3] ----
        // Safe w/o extra barrier: that buffer was last read at iter r-2,
        // and the reduce barrier of iter r-1 (already passed) proves all
        // warps finished iter r-2 entirely.
        if (has_next) {
            const float4* __restrict__ xr =
                reinterpret_cast<const float4*>(x + (size_t)(b + 1) * NS * C_DIM);
            const uint32_t sb = sbase + ((r + 1) % 3) * (ROW_F4 * 16);
#pragma unroll
            for (int n = 0; n < NS; n++) {
                const int idx = n * THREADS + t;
                asm volatile("cp.async.cg.shared.global [%0], [%1], 16;"
                             :: "r"(sb + idx * 16), "l"(xr + idx));
            }
            asm volatile("cp.async.commit_group;");
            asm volatile("cp.async.wait_group 1;" ::: "memory");
        } else {
            asm volatile("cp.async.wait_group 0;" ::: "memory");
        }

        const float4* __restrict__ sb = sx + cur * ROW_F4;

        // ---- pass A: gated agg + bf16 round-trip -> sum of squares ----
        const float4 v0 = sb[0 * THREADS + t];
        const float4 v1 = sb[1 * THREADS + t];
        const float4 v2 = sb[2 * THREADS + t];
        const float4 v3 = sb[3 * THREADS + t];
        float ax = hp0*v0.x + hp1*v1.x + hp2*v2.x + hp3*v3.x;
        float ay = hp0*v0.y + hp1*v1.y + hp2*v2.y + hp3*v3.y;
        float az = hp0*v0.z + hp1*v1.z + hp2*v2.z + hp3*v3.z;
        float aw = hp0*v0.w + hp1*v1.w + hp2*v2.w + hp3*v3.w;
        ax = __bfloat162float(__float2bfloat16(ax));
        ay = __bfloat162float(__float2bfloat16(ay));
        az = __bfloat162float(__float2bfloat16(az));
        aw = __bfloat162float(__float2bfloat16(aw));
        float ss = ax*ax + ay*ay + az*az + aw*aw;

        // ---- warp shuffle reduce -> per-warp partial ----
#pragma unroll
        for (int off = 16; off > 0; off >>= 1)
            ss += __shfl_xor_sync(0xFFFFFFFFu, ss, off);
        if ((t & 31) == 0)
            reinterpret_cast<float*>(red4[par])[t >> 5] = ss;

        __syncthreads();   // the ONE barrier per row

        // ---- every thread sums the 32 partials (broadcast LDS.128) ----
        float4 acc = red4[par][0];
#pragma unroll
        for (int q = 1; q < 8; q++) {
            const float4 p = red4[par][q];
            acc.x += p.x; acc.y += p.y; acc.z += p.z; acc.w += p.w;
        }
        const float tot = (acc.x + acc.y) + (acc.z + acc.w);
        const float inv_rms = rsqrtf(tot * (1.0f / C_DIM) + EPS);

        // ---- pass B: y_norm, 4x4 mix + gated add, float4 stores ----
        const float yx = ax * inv_rms * w4.x;
        const float yy = ay * inv_rms * w4.y;
        const float yz = az * inv_rms * w4.z;
        const float yw = aw * inv_rms * w4.w;

        float4* __restrict__ outr =
            reinterpret_cast<float4*>(out + (size_t)b * NS * C_DIM);
#pragma unroll
        for (int i = 0; i < NS; i++) {
            float4 o;
            o.x = Pr[i][0]*v0.x + Pr[i][1]*v1.x + Pr[i][2]*v2.x + Pr[i][3]*v3.x + hq[i]*yx;
            o.y = Pr[i][0]*v0.y + Pr[i][1]*v1.y + Pr[i][2]*v2.y + Pr[i][3]*v3.y + hq[i]*yy;
            o.z = Pr[i][0]*v0.z + Pr[i][1]*v1.z + Pr[i][2]*v2.z + Pr[i][3]*v3.z + hq[i]*yz;
            o.w = Pr[i][0]*v0.w + Pr[i][1]*v1.w + Pr[i][2]*v2.w + Pr[i][3]*v3.w + hq[i]*yw;
            outr[i * THREADS + t] = o;
        }
    }
}

extern "C" void kernel_launch(void* const* d_in, const int* in_sizes, int n_in,
                              void* d_out, int out_size)
{
    const float* x      = (const float*)d_in[0];  // [8192, 4, 4096]
    const float* w      = (const float*)d_in[1];  // [4096]
    const float* H_pre  = (const float*)d_in[2];  // [4]
    const float* H_post = (const float*)d_in[3];  // [4]
    const float* H_res  = (const float*)d_in[4];  // [4, 4]
    float* out = (float*)d_out;                   // [8192, 4, 4096]

    cudaFuncSetAttribute(mhc_kernel,
                         cudaFuncAttributeMaxDynamicSharedMemorySize, SMEM_BYTES);

    const int B = in_sizes[0] / (NS * C_DIM);     // 8192
    mhc_kernel<<<B / ROWS_PER_CTA, THREADS, SMEM_BYTES>>>(x, w, H_pre, H_post, H_res, out);
}